// round 10
// baseline (speedup 1.0000x reference)
#include <cuda_runtime.h>
#include <stdint.h>

// ---------------------------------------------------------------------------
// octree_level matching the reference's ACTUAL semantics: JAX x64-disabled,
// so _key = (x*4096+y)*4096+z OVERFLOWS int32. Wrapped key bit pattern is
// ((x&255)<<24)|(y<<12)|z, compared SIGNED. Therefore:
//   - parent identity collapses px -> sx = px & 255       (x-alias merge)
//   - signed sort order == lexicographic (sx^128, py, pz) (negatives first)
//   - valid = key >= 0  -> rows with sx >= 128 emit (-1,-1,-1), occ = 0
//   - child occupied  <=>  exists leaf with (x&255, y, z) == (cx, cy, cz)
//
// Bitmaps:
//   parent: 2^26 cells, idx = ((sx^128)<<18)|(py<<9)|pz   (8 MB)
//           word-order enumeration == reference row order (invalid half 1st)
//   leaf:   2^28 cells, idx = ((x&255)<<20)|(y<<10)|z     (32 MB)
//
// kernel_launch adapts to out_size (never writes beyond it):
//   out_size >= 11n : planar [parent_C float (3n) | occupancy float (8n)]
//   out_size ==  8n : occupancy only (float)
//   else            : parent_C only (int32)
// ---------------------------------------------------------------------------

#define LEAF_WORDS (1u << 23)   // 2^28 bits / 32  -> 32 MB
#define PAR_WORDS  (1u << 21)   // 2^26 bits / 32  ->  8 MB
#define NBLOCKS    1024
#define TPB        256
#define WPB        2048         // parent words per block (NBLOCKS*WPB == PAR_WORDS)

__device__ unsigned int g_leaf_bits[LEAF_WORDS];
__device__ unsigned int g_par_bits[PAR_WORDS];
__device__ unsigned int g_block_sums[NBLOCKS];
__device__ unsigned int g_block_excl[NBLOCKS];
__device__ unsigned int g_np;   // total unique wrapped parents (both halves)

__device__ __forceinline__ int clamp1023(float v) {
    int x = (int)floorf(v);
    x = x < 0 ? 0 : x;
    return x > 1023 ? 1023 : x;
}

// --- scatter: parent bitmap only -------------------------------------------
__global__ void k_scatter_par(const float* __restrict__ leaf, int n) {
    int i = blockIdx.x * blockDim.x + threadIdx.x;
    if (i >= n) return;
    int x = clamp1023(leaf[3 * i + 0]);
    int y = clamp1023(leaf[3 * i + 1]);
    int z = clamp1023(leaf[3 * i + 2]);
    unsigned sx = ((unsigned)(x >> 1) & 255u) ^ 128u;          // signed-order index
    unsigned pidx = (sx << 18) | ((unsigned)(y >> 1) << 9) | (unsigned)(z >> 1);
    atomicOr(&g_par_bits[pidx >> 5], 1u << (pidx & 31));
}

// --- scatter: both bitmaps -------------------------------------------------
__global__ void k_scatter_full(const float* __restrict__ leaf, int n) {
    int i = blockIdx.x * blockDim.x + threadIdx.x;
    if (i >= n) return;
    int x = clamp1023(leaf[3 * i + 0]);
    int y = clamp1023(leaf[3 * i + 1]);
    int z = clamp1023(leaf[3 * i + 2]);
    unsigned lidx = (((unsigned)x & 255u) << 20) | ((unsigned)y << 10) | (unsigned)z;
    atomicOr(&g_leaf_bits[lidx >> 5], 1u << (lidx & 31));
    unsigned sx = ((unsigned)(x >> 1) & 255u) ^ 128u;
    unsigned pidx = (sx << 18) | ((unsigned)(y >> 1) << 9) | (unsigned)(z >> 1);
    atomicOr(&g_par_bits[pidx >> 5], 1u << (pidx & 31));
}

// --- per-block popcount of parent bitmap -----------------------------------
__global__ void k_count() {
    __shared__ unsigned int warp_sums[TPB / 32];
    unsigned t = threadIdx.x;
    unsigned base = blockIdx.x * WPB;
    unsigned s = 0;
#pragma unroll
    for (int u = 0; u < WPB / TPB; u++)
        s += __popc(g_par_bits[base + u * TPB + t]);
#pragma unroll
    for (int o = 16; o; o >>= 1) s += __shfl_down_sync(0xffffffffu, s, o);
    if ((t & 31) == 0) warp_sums[t >> 5] = s;
    __syncthreads();
    if (t == 0) {
        unsigned tot = 0;
#pragma unroll
        for (int w = 0; w < TPB / 32; w++) tot += warp_sums[w];
        g_block_sums[blockIdx.x] = tot;
    }
}

// --- exclusive scan of the 1024 block sums (single block) ------------------
__global__ void k_scan() {
    __shared__ unsigned int sh[NBLOCKS];
    unsigned t = threadIdx.x;
    unsigned v = g_block_sums[t];
    sh[t] = v;
    __syncthreads();
    for (int o = 1; o < NBLOCKS; o <<= 1) {
        unsigned x = (t >= (unsigned)o) ? sh[t - o] : 0u;
        __syncthreads();
        sh[t] += x;
        __syncthreads();
    }
    g_block_excl[t] = sh[t] - v;
    if (t == NBLOCKS - 1) g_np = sh[t];
}

// ---------------------------------------------------------------------------
// Fused compaction + emit in reference row order.
// MODE 0: int32 coords only; MODE 1: float coords + occ (planar, occ at 3n);
// MODE 2: float occ only at offset 0.
// ---------------------------------------------------------------------------
template <int MODE>
__global__ void k_emit(void* __restrict__ out_raw, int n) {
    __shared__ unsigned int iter_base;
    __shared__ unsigned int warp_sc[TPB / 32];
    unsigned t = threadIdx.x;
    unsigned lane = t & 31, wrp = t >> 5;
    if (t == 0) iter_base = g_block_excl[blockIdx.x];
    __syncthreads();

    unsigned base = blockIdx.x * WPB;
    int*   out_i   = (int*)out_raw;
    float* out_f   = (float*)out_raw;
    float* out_occ = (MODE == 1) ? out_f + 3ull * (unsigned long long)n : out_f;

    for (int u = 0; u < WPB / TPB; u++) {
        unsigned w = base + u * TPB + t;
        unsigned bits = g_par_bits[w];
        unsigned p = __popc(bits);

        unsigned incl = p;                        // warp-inclusive scan
#pragma unroll
        for (int o = 1; o < 32; o <<= 1) {
            unsigned x = __shfl_up_sync(0xffffffffu, incl, o);
            if (lane >= (unsigned)o) incl += x;
        }
        if (lane == 31) warp_sc[wrp] = incl;
        __syncthreads();

        unsigned warp_off = 0;
        for (unsigned ww = 0; ww < wrp; ww++) warp_off += warp_sc[ww];
        unsigned excl = warp_off + incl - p;
        unsigned r = iter_base + excl;

        unsigned bb = bits;
        while (bb) {
            int b = __ffs(bb) - 1;
            bb &= bb - 1;
            unsigned idx = (w << 5) | (unsigned)b;
            unsigned sp = idx >> 18;              // sx ^ 128 (signed-order)
            unsigned py = (idx >> 9) & 511u;
            unsigned pz = idx & 511u;
            bool val = (sp >= 128u);              // key >= 0 half
            unsigned sx = sp ^ 128u;              // real px&255 for valid rows

            if (MODE == 0) {
                unsigned long long r3 = 3ull * r;
                if (val) {
                    out_i[r3 + 0] = (int)sx;
                    out_i[r3 + 1] = (int)py;
                    out_i[r3 + 2] = (int)pz;
                } else {
                    out_i[r3 + 0] = -1; out_i[r3 + 1] = -1; out_i[r3 + 2] = -1;
                }
            } else if (MODE == 1) {
                unsigned long long r3 = 3ull * r;
                if (val) {
                    out_f[r3 + 0] = (float)sx;
                    out_f[r3 + 1] = (float)py;
                    out_f[r3 + 2] = (float)pz;
                } else {
                    out_f[r3 + 0] = -1.0f; out_f[r3 + 1] = -1.0f; out_f[r3 + 2] = -1.0f;
                }
            }

            if (MODE != 0) {
                unsigned long long r8 = 8ull * r;
                if (val) {
                    unsigned cz = pz << 1;
                    unsigned bit0 = cz & 31;
                    unsigned zw = cz >> 5;
                    unsigned cx0 = sx << 1, cy0 = py << 1;
#pragma unroll
                    for (int ij = 0; ij < 4; ij++) {
                        unsigned cx = cx0 + (unsigned)(ij >> 1);
                        unsigned cy = cy0 + (unsigned)(ij & 1);
                        unsigned lw = (cx << 15) | (cy << 5) | zw;   // leaf word idx
                        unsigned lv = g_leaf_bits[lw];
                        out_occ[r8 + (unsigned)ij * 2 + 0] = ((lv >> bit0) & 1u) ? 1.0f : 0.0f;
                        out_occ[r8 + (unsigned)ij * 2 + 1] = ((lv >> (bit0 + 1)) & 1u) ? 1.0f : 0.0f;
                    }
                } else {
#pragma unroll
                    for (int k = 0; k < 8; k++) out_occ[r8 + (unsigned)k] = 0.0f;
                }
            }
            r++;
        }
        __syncthreads();
        if (t == TPB - 1) iter_base += warp_off + incl;   // block total this iter
        __syncthreads();
    }
}

// --- pad tail rows [np, n): parent_C = -1, occupancy = 0 -------------------
template <int MODE>
__global__ void k_tail(void* __restrict__ out_raw, int n) {
    unsigned np = g_np;
    unsigned i = blockIdx.x * blockDim.x + threadIdx.x;
    if (i >= (unsigned)n || i < np) return;
    int*   out_i = (int*)out_raw;
    float* out_f = (float*)out_raw;
    if (MODE == 0) {
        unsigned long long i3 = 3ull * i;
        out_i[i3 + 0] = -1; out_i[i3 + 1] = -1; out_i[i3 + 2] = -1;
    } else if (MODE == 1) {
        unsigned long long i3 = 3ull * i;
        out_f[i3 + 0] = -1.0f; out_f[i3 + 1] = -1.0f; out_f[i3 + 2] = -1.0f;
        float* oo = out_f + 3ull * (unsigned long long)n + 8ull * i;
#pragma unroll
        for (int k = 0; k < 8; k++) oo[k] = 0.0f;
    } else {
        float* oo = out_f + 8ull * i;
#pragma unroll
        for (int k = 0; k < 8; k++) oo[k] = 0.0f;
    }
}

extern "C" void kernel_launch(void* const* d_in, const int* in_sizes, int n_in,
                              void* d_out, int out_size) {
    const float* leaf = (const float*)d_in[0];
    int n = in_sizes[0] / 3;
    int grid_n = (n + TPB - 1) / TPB;

    void* pp = nullptr;
    cudaGetSymbolAddress(&pp, g_par_bits);
    cudaMemsetAsync(pp, 0, (size_t)PAR_WORDS * sizeof(unsigned int));

    bool need_occ = (out_size >= 11 * n) || (out_size == 8 * n);
    if (need_occ) {
        void* pl = nullptr;
        cudaGetSymbolAddress(&pl, g_leaf_bits);
        cudaMemsetAsync(pl, 0, (size_t)LEAF_WORDS * sizeof(unsigned int));
        k_scatter_full<<<grid_n, TPB>>>(leaf, n);
    } else {
        k_scatter_par<<<grid_n, TPB>>>(leaf, n);
    }

    k_count<<<NBLOCKS, TPB>>>();
    k_scan<<<1, NBLOCKS>>>();

    if (out_size >= 11 * n) {
        k_emit<1><<<NBLOCKS, TPB>>>(d_out, n);
        k_tail<1><<<grid_n, TPB>>>(d_out, n);
    } else if (out_size == 8 * n) {
        k_emit<2><<<NBLOCKS, TPB>>>(d_out, n);
        k_tail<2><<<grid_n, TPB>>>(d_out, n);
    } else {
        k_emit<0><<<NBLOCKS, TPB>>>(d_out, n);
        k_tail<0><<<grid_n, TPB>>>(d_out, n);
    }
}

// round 11
// speedup vs baseline: 1.5324x; 1.5324x over previous
#include <cuda_runtime.h>
#include <stdint.h>

// ---------------------------------------------------------------------------
// octree_level matching the reference's ACTUAL semantics (JAX x64 disabled:
// _key overflows int32; wrapped key = ((x&255)<<24)|(y<<12)|z, signed order).
//   - parent identity collapses px -> sx = px & 255
//   - signed sort == lexicographic (sx^128, py, pz), negative half first
//   - rows with key<0 (sx>=128) are invalid: coords (-1,-1,-1), occ 0
//   - child (i,j,k) of valid parent (sx,py,pz) occupied <=> exists leaf with
//     (x&255, y, z) == (2sx+i, 2py+j, 2pz+k)        (sx<128 so 2sx+i<256)
//
// Bitmaps:
//   parent: 2^26 cells, idx = (sp<<18)|(py<<9)|pz, sp=(px&255)^128 (8 MB)
//           word-order enumeration == reference row order
//   leaf2 (child-grouped probe table): bit = (cell<<3)|m, 2^28 bits (32 MB)
//           cell = (((x&255)>>1)<<18)|((y>>1)<<9)|(z>>1), m = 4(x&1)+2(y&1)+(z&1)
//           -> 8-child occupancy of a parent = ONE byte; the 8 leaf2 words a
//              32-parent word needs are one contiguous 32B sector.
//
// Output split: rows [0, invN) (negative-key half) and [np, n) (pad) are the
// constant (-1,-1,-1)/0 pattern -> streaming k_fill; k_emit covers only the
// valid half (blocks >= NBLOCKS/2, boundary exact: w=2^20 <=> sp=128).
//
// kernel_launch adapts to out_size (never writes beyond it):
//   out_size >= 11n : planar [parent_C float (3n) | occupancy float (8n)]
//   out_size ==  8n : occupancy only (float)
//   else            : parent_C only (int32)
// ---------------------------------------------------------------------------

#define LEAF2_WORDS (1u << 23)  // 2^28 bits -> 32 MB
#define PAR_WORDS   (1u << 21)  // 2^26 bits ->  8 MB
#define NBLOCKS     1024
#define TPB         256
#define WPB         2048        // parent words per block (NBLOCKS*WPB == PAR_WORDS)

__device__ unsigned int g_leaf2[LEAF2_WORDS];
__device__ unsigned int g_par_bits[PAR_WORDS];
__device__ unsigned int g_block_sums[NBLOCKS];
__device__ unsigned int g_block_excl[NBLOCKS];
__device__ unsigned int g_np;    // total rows (invalid + valid)

__device__ __forceinline__ int clamp1023(float v) {
    int x = (int)floorf(v);
    x = x < 0 ? 0 : x;
    return x > 1023 ? 1023 : x;
}

// --- scatter: parent bitmap only -------------------------------------------
__global__ void k_scatter_par(const float* __restrict__ leaf, int n) {
    int i = blockIdx.x * blockDim.x + threadIdx.x;
    if (i >= n) return;
    int x = clamp1023(leaf[3 * i + 0]);
    int y = clamp1023(leaf[3 * i + 1]);
    int z = clamp1023(leaf[3 * i + 2]);
    unsigned sp = (((unsigned)(x >> 1)) & 255u) ^ 128u;
    unsigned pidx = (sp << 18) | ((unsigned)(y >> 1) << 9) | (unsigned)(z >> 1);
    atomicOr(&g_par_bits[pidx >> 5], 1u << (pidx & 31));
}

// --- scatter: parent bitmap + child-grouped probe table --------------------
__global__ void k_scatter_full(const float* __restrict__ leaf, int n) {
    int i = blockIdx.x * blockDim.x + threadIdx.x;
    if (i >= n) return;
    int x = clamp1023(leaf[3 * i + 0]);
    int y = clamp1023(leaf[3 * i + 1]);
    int z = clamp1023(leaf[3 * i + 2]);
    // probe table: keyed by the (valid) parent that would query this leaf
    unsigned sxp = ((unsigned)(x & 255)) >> 1;                     // 0..127
    unsigned cell = (sxp << 18) | ((unsigned)(y >> 1) << 9) | (unsigned)(z >> 1);
    unsigned m = (((unsigned)x & 1u) << 2) | (((unsigned)y & 1u) << 1) | ((unsigned)z & 1u);
    atomicOr(&g_leaf2[cell >> 2], 1u << (((cell & 3u) << 3) | m));
    // parent enumeration bitmap (own cell, signed order)
    unsigned sp = (((unsigned)(x >> 1)) & 255u) ^ 128u;
    unsigned pidx = (sp << 18) | ((unsigned)(y >> 1) << 9) | (unsigned)(z >> 1);
    atomicOr(&g_par_bits[pidx >> 5], 1u << (pidx & 31));
}

// --- per-block popcount of parent bitmap -----------------------------------
__global__ void k_count() {
    __shared__ unsigned int warp_sums[TPB / 32];
    unsigned t = threadIdx.x;
    unsigned base = blockIdx.x * WPB;
    unsigned s = 0;
#pragma unroll
    for (int u = 0; u < WPB / TPB; u++)
        s += __popc(g_par_bits[base + u * TPB + t]);
#pragma unroll
    for (int o = 16; o; o >>= 1) s += __shfl_down_sync(0xffffffffu, s, o);
    if ((t & 31) == 0) warp_sums[t >> 5] = s;
    __syncthreads();
    if (t == 0) {
        unsigned tot = 0;
#pragma unroll
        for (int w = 0; w < TPB / 32; w++) tot += warp_sums[w];
        g_block_sums[blockIdx.x] = tot;
    }
}

// --- exclusive scan of the 1024 block sums (single block) ------------------
__global__ void k_scan() {
    __shared__ unsigned int sh[NBLOCKS];
    unsigned t = threadIdx.x;
    unsigned v = g_block_sums[t];
    sh[t] = v;
    __syncthreads();
    for (int o = 1; o < NBLOCKS; o <<= 1) {
        unsigned x = (t >= (unsigned)o) ? sh[t - o] : 0u;
        __syncthreads();
        sh[t] += x;
        __syncthreads();
    }
    g_block_excl[t] = sh[t] - v;
    if (t == NBLOCKS - 1) g_np = sh[t];
}

// ---------------------------------------------------------------------------
// Emit VALID half only (grid = NBLOCKS/2, block b -> parent block 512+b).
// MODE 0: int32 coords; MODE 1: float coords + occ (occ at out+3n);
// MODE 2: float occ only at offset 0.
// ---------------------------------------------------------------------------
template <int MODE>
__global__ void k_emit(void* __restrict__ out_raw, int n) {
    __shared__ unsigned int iter_base;
    __shared__ unsigned int warp_sc[TPB / 32];
    unsigned t = threadIdx.x;
    unsigned lane = t & 31, wrp = t >> 5;
    unsigned pb = blockIdx.x + NBLOCKS / 2;            // valid-half block id
    if (t == 0) iter_base = g_block_excl[pb];
    __syncthreads();

    unsigned base = pb * WPB;
    int*   out_i   = (int*)out_raw;
    float* out_f   = (float*)out_raw;
    float* out_occ = (MODE == 1) ? out_f + 3ull * (unsigned long long)n : out_f;

    for (int u = 0; u < WPB / TPB; u++) {
        unsigned w = base + u * TPB + t;
        unsigned bits = g_par_bits[w];
        unsigned p = __popc(bits);

        unsigned incl = p;                             // warp-inclusive scan
#pragma unroll
        for (int o = 1; o < 32; o <<= 1) {
            unsigned x = __shfl_up_sync(0xffffffffu, incl, o);
            if (lane >= (unsigned)o) incl += x;
        }
        if (lane == 31) warp_sc[wrp] = incl;
        __syncthreads();

        unsigned warp_off = 0;
        for (unsigned ww = 0; ww < wrp; ww++) warp_off += warp_sc[ww];
        unsigned r = iter_base + warp_off + incl - p;

        unsigned bb = bits;
        while (bb) {
            int b = __ffs(bb) - 1;
            bb &= bb - 1;
            unsigned idx = (w << 5) | (unsigned)b;     // (sp<<18)|(py<<9)|pz, sp>=128
            unsigned cell = idx - (1u << 25);          // (sx<<18)|(py<<9)|pz, sx<128
            unsigned sx = cell >> 18;
            unsigned py = (cell >> 9) & 511u;
            unsigned pz = cell & 511u;

            if (MODE == 0) {
                unsigned long long r3 = 3ull * r;
                out_i[r3 + 0] = (int)sx;
                out_i[r3 + 1] = (int)py;
                out_i[r3 + 2] = (int)pz;
            } else if (MODE == 1) {
                unsigned long long r3 = 3ull * r;
                out_f[r3 + 0] = (float)sx;
                out_f[r3 + 1] = (float)py;
                out_f[r3 + 2] = (float)pz;
            }

            if (MODE != 0) {
                unsigned lw = g_leaf2[cell >> 2];
                unsigned byt = (lw >> ((cell & 3u) << 3)) & 255u;
                float4 o0 = make_float4((float)(byt & 1u), (float)((byt >> 1) & 1u),
                                        (float)((byt >> 2) & 1u), (float)((byt >> 3) & 1u));
                float4 o1 = make_float4((float)((byt >> 4) & 1u), (float)((byt >> 5) & 1u),
                                        (float)((byt >> 6) & 1u), (float)((byt >> 7) & 1u));
                float4* dst = (float4*)(out_occ + 8ull * r);
                dst[0] = o0;
                dst[1] = o1;
            }
            r++;
        }
        __syncthreads();
        if (t == TPB - 1) iter_base += warp_off + incl;   // block total this iter
        __syncthreads();
    }
}

// ---------------------------------------------------------------------------
// Streaming constant fill: rows [0, invN) (negative-key half) and [np, n)
// (pad) get coords = -1, occupancy = 0. invN = g_block_excl[NBLOCKS/2].
// ---------------------------------------------------------------------------
template <int MODE>
__global__ void k_fill(void* __restrict__ out_raw, int n) {
    unsigned invN = g_block_excl[NBLOCKS / 2];
    unsigned np = g_np;
    unsigned i = blockIdx.x * blockDim.x + threadIdx.x;
    if (i >= (unsigned)n) return;
    if (i >= invN && i < np) return;                   // valid row: emit owns it

    int*   out_i = (int*)out_raw;
    float* out_f = (float*)out_raw;
    if (MODE == 0) {
        unsigned long long i3 = 3ull * i;
        out_i[i3 + 0] = -1; out_i[i3 + 1] = -1; out_i[i3 + 2] = -1;
    } else if (MODE == 1) {
        unsigned long long i3 = 3ull * i;
        out_f[i3 + 0] = -1.0f; out_f[i3 + 1] = -1.0f; out_f[i3 + 2] = -1.0f;
        float4* oo = (float4*)(out_f + 3ull * (unsigned long long)n + 8ull * i);
        float4 z = make_float4(0.f, 0.f, 0.f, 0.f);
        oo[0] = z; oo[1] = z;
    } else {
        float4* oo = (float4*)(out_f + 8ull * i);
        float4 z = make_float4(0.f, 0.f, 0.f, 0.f);
        oo[0] = z; oo[1] = z;
    }
}

extern "C" void kernel_launch(void* const* d_in, const int* in_sizes, int n_in,
                              void* d_out, int out_size) {
    const float* leaf = (const float*)d_in[0];
    int n = in_sizes[0] / 3;
    int grid_n = (n + TPB - 1) / TPB;

    void* pp = nullptr;
    cudaGetSymbolAddress(&pp, g_par_bits);
    cudaMemsetAsync(pp, 0, (size_t)PAR_WORDS * sizeof(unsigned int));

    bool need_occ = (out_size >= 11 * n) || (out_size == 8 * n);
    if (need_occ) {
        void* pl = nullptr;
        cudaGetSymbolAddress(&pl, g_leaf2);
        cudaMemsetAsync(pl, 0, (size_t)LEAF2_WORDS * sizeof(unsigned int));
        k_scatter_full<<<grid_n, TPB>>>(leaf, n);
    } else {
        k_scatter_par<<<grid_n, TPB>>>(leaf, n);
    }

    k_count<<<NBLOCKS, TPB>>>();
    k_scan<<<1, NBLOCKS>>>();

    if (out_size >= 11 * n) {
        k_emit<1><<<NBLOCKS / 2, TPB>>>(d_out, n);
        k_fill<1><<<grid_n, TPB>>>(d_out, n);
    } else if (out_size == 8 * n) {
        k_emit<2><<<NBLOCKS / 2, TPB>>>(d_out, n);
        k_fill<2><<<grid_n, TPB>>>(d_out, n);
    } else {
        k_emit<0><<<NBLOCKS / 2, TPB>>>(d_out, n);
        k_fill<0><<<grid_n, TPB>>>(d_out, n);
    }
}